// round 2
// baseline (speedup 1.0000x reference)
#include <cuda_runtime.h>

#define NN 1024
#define BB 64
#define CC 128
#define HH 64
#define ED 16
#define BCDIM (BB*CC)   /* 8192 */

// Scratch (device globals — no allocation allowed in kernel_launch)
__device__ float g_A [NN*NN];          // 4 MB   adjacency (row-softmaxed)
__device__ float g_X [NN*BB*CC];       // 32 MB  concat(x,state) in (n,b,c)
__device__ float g_X2[NN*BB*CC];       // 32 MB  candidate concat(x, z*state)
__device__ float g_Y1[NN*BB*CC];       // 32 MB  A @ X
__device__ float g_Y2[NN*BB*CC];       // 32 MB  A @ Y1
__device__ float g_W [NN*3*CC*CC];     // 192 MB per-node weights (gate; reused for upd)
__device__ float g_R [NN*BB*HH];       // 16 MB  r gate in (n,b,h)

// ---------------------------------------------------------------------------
// Build X[n, b*128 + c] = concat(x, state)[b, n, c]
__global__ void build_X_kernel(const float* __restrict__ x,
                               const float* __restrict__ st,
                               float* __restrict__ X) {
    int idx = blockIdx.x * 256 + threadIdx.x;     // total 8,388,608
    int c = idx & 127;
    int b = (idx >> 7) & 63;
    int n = idx >> 13;
    float v = (c < HH) ? x [(size_t)b * (NN*HH) + n*HH + c]
                       : st[(size_t)b * (NN*HH) + n*HH + (c - HH)];
    X[idx] = v;
}

// ---------------------------------------------------------------------------
// A = softmax(relu(E E^T), axis=1). One CTA (256 threads) per row.
__global__ void compute_A_kernel(const float* __restrict__ E,
                                 float* __restrict__ A) {
    int i = blockIdx.x;
    int tid = threadIdx.x;
    __shared__ float Ei[ED];
    __shared__ float red[256];
    if (tid < ED) Ei[tid] = E[i*ED + tid];
    __syncthreads();

    float v[4];
    float vmax = 0.0f;   // relu => >= 0, diagonal > 0
#pragma unroll
    for (int p = 0; p < 4; p++) {
        int j = tid + p * 256;
        const float4* Ej = (const float4*)(E + (size_t)j * ED);
        float4 e0 = Ej[0], e1 = Ej[1], e2 = Ej[2], e3 = Ej[3];
        float d = Ei[0]*e0.x + Ei[1]*e0.y + Ei[2]*e0.z + Ei[3]*e0.w
                + Ei[4]*e1.x + Ei[5]*e1.y + Ei[6]*e1.z + Ei[7]*e1.w
                + Ei[8]*e2.x + Ei[9]*e2.y + Ei[10]*e2.z + Ei[11]*e2.w
                + Ei[12]*e3.x + Ei[13]*e3.y + Ei[14]*e3.z + Ei[15]*e3.w;
        d = fmaxf(d, 0.0f);
        v[p] = d;
        vmax = fmaxf(vmax, d);
    }
    red[tid] = vmax; __syncthreads();
    for (int s = 128; s > 0; s >>= 1) {
        if (tid < s) red[tid] = fmaxf(red[tid], red[tid + s]);
        __syncthreads();
    }
    vmax = red[0];
    __syncthreads();
    float lsum = 0.0f;
#pragma unroll
    for (int p = 0; p < 4; p++) { v[p] = __expf(v[p] - vmax); lsum += v[p]; }
    red[tid] = lsum; __syncthreads();
    for (int s = 128; s > 0; s >>= 1) {
        if (tid < s) red[tid] += red[tid + s];
        __syncthreads();
    }
    float inv = 1.0f / red[0];
#pragma unroll
    for (int p = 0; p < 4; p++)
        A[(size_t)i * NN + tid + p * 256] = v[p] * inv;
}

// ---------------------------------------------------------------------------
// SGEMM: C[M,N] = A[M,K] @ B[K,N], row-major. M,N mult of 128, K mult of 8.
// 128x128 tile, BK=8, 256 threads, 8x8 register micro-tile.
__global__ __launch_bounds__(256, 2)
void sgemm_kernel(const float* __restrict__ A, const float* __restrict__ B,
                  float* __restrict__ C, int M, int N, int K) {
    __shared__ float As[8][128];
    __shared__ float Bs[8][128];
    int tid = threadIdx.x;
    int block_row = blockIdx.y * 128;
    int block_col = blockIdx.x * 128;

    int a_row = tid >> 1;
    int a_col = (tid & 1) * 4;
    int b_row = tid >> 5;
    int b_col = (tid & 31) * 4;

    int ty = tid >> 4, tx = tid & 15;
    float acc[8][8];
#pragma unroll
    for (int i = 0; i < 8; i++)
#pragma unroll
        for (int j = 0; j < 8; j++) acc[i][j] = 0.0f;

    const float* Aptr = A + (size_t)block_row * K;
    const float* Bptr = B + block_col;

    for (int k0 = 0; k0 < K; k0 += 8) {
        float4 av = *(const float4*)(Aptr + (size_t)a_row * K + k0 + a_col);
        As[a_col + 0][a_row] = av.x;
        As[a_col + 1][a_row] = av.y;
        As[a_col + 2][a_row] = av.z;
        As[a_col + 3][a_row] = av.w;
        float4 bv = *(const float4*)(Bptr + (size_t)(k0 + b_row) * N + b_col);
        *(float4*)&Bs[b_row][b_col] = bv;
        __syncthreads();
#pragma unroll
        for (int kk = 0; kk < 8; kk++) {
            float areg[8], breg[8];
#pragma unroll
            for (int i = 0; i < 8; i++) areg[i] = As[kk][ty * 8 + i];
#pragma unroll
            for (int j = 0; j < 8; j++) breg[j] = Bs[kk][tx * 8 + j];
#pragma unroll
            for (int i = 0; i < 8; i++)
#pragma unroll
                for (int j = 0; j < 8; j++)
                    acc[i][j] += areg[i] * breg[j];
        }
        __syncthreads();
    }
#pragma unroll
    for (int i = 0; i < 8; i++) {
        size_t row = block_row + ty * 8 + i;
#pragma unroll
        for (int j = 0; j < 8; j += 4) {
            int col = block_col + tx * 8 + j;
            float4 v = make_float4(acc[i][j], acc[i][j+1], acc[i][j+2], acc[i][j+3]);
            *(float4*)(C + row * N + col) = v;
        }
    }
}

// ---------------------------------------------------------------------------
// W[n, :] = sum_e E[n,e] * Wp[e, :]   (Wp viewed as (16, TC)),  TC = 384*O
// Grid: (TC/1024, 64 node-groups of 16). 256 threads.
__global__ void build_W_kernel(const float* __restrict__ Wp,
                               const float* __restrict__ E,
                               float* __restrict__ W, int TC) {
    int ng = blockIdx.y;
    int cbase = blockIdx.x * 1024;
    __shared__ float Es[16][16];
    {
        int nn = threadIdx.x >> 4, e = threadIdx.x & 15;
        if (threadIdx.x < 256) Es[nn][e] = E[(ng * 16 + nn) * ED + e];
    }
    __syncthreads();
    for (int cc = 0; cc < 1024; cc += 256) {
        int c = cbase + cc + threadIdx.x;
        float wp[16];
#pragma unroll
        for (int e = 0; e < 16; e++) wp[e] = Wp[(size_t)e * TC + c];
#pragma unroll
        for (int nn = 0; nn < 16; nn++) {
            float a = 0.0f;
#pragma unroll
            for (int e = 0; e < 16; e++) a += Es[nn][e] * wp[e];
            W[(size_t)(ng * 16 + nn) * TC + c] = a;
        }
    }
}

// ---------------------------------------------------------------------------
// Per-node gate GEMM + sigmoid epilogue. One CTA per node.
// Xg(64 x 384) = [X[n] | Y1[n] | 2*Y2[n]-X[n]],   Out = Xg @ W[n] + bias[n]
// z = sigmoid(out[:, :64]); r = sigmoid(out[:, 64:])
// Writes X2 (candidate concat) and R.
__global__ __launch_bounds__(256)
void pernode_gate_kernel(const float* __restrict__ X, const float* __restrict__ Y1,
                         const float* __restrict__ Y2, const float* __restrict__ W,
                         const float* __restrict__ E,  const float* __restrict__ bpool,
                         float* __restrict__ X2, float* __restrict__ R) {
    int n = blockIdx.x;
    __shared__ float xs[64][17];
    __shared__ float ws[16][128];
    __shared__ float bias[128];

    int tid = threadIdx.x;
    if (tid < 128) {
        float a = 0.0f;
#pragma unroll
        for (int e = 0; e < 16; e++) a += E[n*ED + e] * bpool[e*128 + tid];
        bias[tid] = a;
    }

    const float* Xn  = X  + (size_t)n * BCDIM;
    const float* Y1n = Y1 + (size_t)n * BCDIM;
    const float* Y2n = Y2 + (size_t)n * BCDIM;
    const float* Wn  = W  + (size_t)n * (3*CC*CC);

    int ty = tid >> 4, tx = tid & 15;   // rows ty*4..+3, cols tx*8..+7
    float acc[4][8];
#pragma unroll
    for (int i = 0; i < 4; i++)
#pragma unroll
        for (int j = 0; j < 8; j++) acc[i][j] = 0.0f;

    int lkk = tid & 15;
    int lb0 = tid >> 4;
    int wc  = tid & 127;
    int wk0 = tid >> 7;

    for (int kc0 = 0; kc0 < 384; kc0 += 16) {
        int kseg = kc0 >> 7;       // which Chebyshev term
        int i0 = kc0 & 127;
        // load Xg chunk (64 b-rows x 16 k) into xs[b][kk]
#pragma unroll
        for (int p = 0; p < 4; p++) {
            int b = lb0 + p * 16;
            int off = b * 128 + i0 + lkk;
            float v;
            if (kseg == 0)      v = Xn[off];
            else if (kseg == 1) v = Y1n[off];
            else                v = 2.0f * Y2n[off] - Xn[off];
            xs[b][lkk] = v;
        }
        // load W chunk (16 x 128)
#pragma unroll
        for (int kk = wk0; kk < 16; kk += 2)
            ws[kk][wc] = Wn[(kc0 + kk) * 128 + wc];
        __syncthreads();
#pragma unroll
        for (int kk = 0; kk < 16; kk++) {
            float a0 = xs[ty*4+0][kk], a1 = xs[ty*4+1][kk];
            float a2 = xs[ty*4+2][kk], a3 = xs[ty*4+3][kk];
            float br[8];
#pragma unroll
            for (int j = 0; j < 8; j++) br[j] = ws[kk][tx*8 + j];
#pragma unroll
            for (int j = 0; j < 8; j++) {
                acc[0][j] += a0 * br[j];
                acc[1][j] += a1 * br[j];
                acc[2][j] += a2 * br[j];
                acc[3][j] += a3 * br[j];
            }
        }
        __syncthreads();
    }

    float* X2n = X2 + (size_t)n * BCDIM;
    float* Rn  = R  + (size_t)n * (BB*HH);
#pragma unroll
    for (int i = 0; i < 4; i++) {
        int b = ty*4 + i;
#pragma unroll
        for (int j = 0; j < 8; j++) {
            int c = tx*8 + j;
            float v = acc[i][j] + bias[c];
            float s = 1.0f / (1.0f + __expf(-v));
            if (c < HH) {
                // z gate: candidate state part + copy x part
                float st = Xn[b*128 + HH + c];
                X2n[b*128 + HH + c] = s * st;
                X2n[b*128 + c]      = Xn[b*128 + c];
            } else {
                Rn[b*HH + (c - HH)] = s;
            }
        }
    }
}

// ---------------------------------------------------------------------------
// Per-node update GEMM + tanh + GRU combine. One CTA per node, out cols = 64.
__global__ __launch_bounds__(256)
void pernode_upd_kernel(const float* __restrict__ X2, const float* __restrict__ Y1,
                        const float* __restrict__ Y2, const float* __restrict__ W,
                        const float* __restrict__ E,  const float* __restrict__ bpool,
                        const float* __restrict__ R,  const float* __restrict__ X,
                        float* __restrict__ out) {
    int n = blockIdx.x;
    __shared__ float xs[64][17];
    __shared__ float ws[16][64];
    __shared__ float bias[64];

    int tid = threadIdx.x;
    if (tid < 64) {
        float a = 0.0f;
#pragma unroll
        for (int e = 0; e < 16; e++) a += E[n*ED + e] * bpool[e*64 + tid];
        bias[tid] = a;
    }

    const float* Xn  = X2 + (size_t)n * BCDIM;
    const float* Y1n = Y1 + (size_t)n * BCDIM;
    const float* Y2n = Y2 + (size_t)n * BCDIM;
    const float* Wn  = W  + (size_t)n * (3*CC*HH);

    int ty = tid >> 4, tx = tid & 15;   // rows ty*4..+3, cols tx*4..+3
    float acc[4][4];
#pragma unroll
    for (int i = 0; i < 4; i++)
#pragma unroll
        for (int j = 0; j < 4; j++) acc[i][j] = 0.0f;

    int lkk = tid & 15;
    int lb0 = tid >> 4;
    int wc  = tid & 63;
    int wk0 = tid >> 6;

    for (int kc0 = 0; kc0 < 384; kc0 += 16) {
        int kseg = kc0 >> 7;
        int i0 = kc0 & 127;
#pragma unroll
        for (int p = 0; p < 4; p++) {
            int b = lb0 + p * 16;
            int off = b * 128 + i0 + lkk;
            float v;
            if (kseg == 0)      v = Xn[off];
            else if (kseg == 1) v = Y1n[off];
            else                v = 2.0f * Y2n[off] - Xn[off];
            xs[b][lkk] = v;
        }
#pragma unroll
        for (int kk = wk0; kk < 16; kk += 4)
            ws[kk][wc] = Wn[(kc0 + kk) * 64 + wc];
        __syncthreads();
#pragma unroll
        for (int kk = 0; kk < 16; kk++) {
            float a0 = xs[ty*4+0][kk], a1 = xs[ty*4+1][kk];
            float a2 = xs[ty*4+2][kk], a3 = xs[ty*4+3][kk];
            float br[4];
#pragma unroll
            for (int j = 0; j < 4; j++) br[j] = ws[kk][tx*4 + j];
#pragma unroll
            for (int j = 0; j < 4; j++) {
                acc[0][j] += a0 * br[j];
                acc[1][j] += a1 * br[j];
                acc[2][j] += a2 * br[j];
                acc[3][j] += a3 * br[j];
            }
        }
        __syncthreads();
    }

    const float* Rn = R + (size_t)n * (BB*HH);
    const float* Xfull = X + (size_t)n * BCDIM;   // original concat: state at cols 64:128
#pragma unroll
    for (int i = 0; i < 4; i++) {
        int b = ty*4 + i;
#pragma unroll
        for (int j = 0; j < 4; j++) {
            int c = tx*4 + j;
            float hc = tanhf(acc[i][j] + bias[c]);
            float r  = Rn[b*HH + c];
            float st = Xfull[b*128 + HH + c];
            out[(size_t)b * (NN*HH) + n*HH + c] = r * st + (1.0f - r) * hc;
        }
    }
}

// ---------------------------------------------------------------------------
extern "C" void kernel_launch(void* const* d_in, const int* in_sizes, int n_in,
                              void* d_out, int out_size) {
    const float* x     = (const float*)d_in[0];
    const float* state = (const float*)d_in[1];
    const float* E     = (const float*)d_in[2];
    const float* gWp   = (const float*)d_in[3];
    const float* gbp   = (const float*)d_in[4];
    const float* uWp   = (const float*)d_in[5];
    const float* ubp   = (const float*)d_in[6];
    float* out = (float*)d_out;

    float *A, *X, *X2, *Y1, *Y2, *W, *R;
    cudaGetSymbolAddress((void**)&A,  g_A);
    cudaGetSymbolAddress((void**)&X,  g_X);
    cudaGetSymbolAddress((void**)&X2, g_X2);
    cudaGetSymbolAddress((void**)&Y1, g_Y1);
    cudaGetSymbolAddress((void**)&Y2, g_Y2);
    cudaGetSymbolAddress((void**)&W,  g_W);
    cudaGetSymbolAddress((void**)&R,  g_R);

    // 1. layouts + adjacency
    build_X_kernel<<<NN*BB*CC/256, 256>>>(x, state, X);
    compute_A_kernel<<<NN, 256>>>(E, A);

    dim3 gemm_grid(BCDIM/128, NN/128);   // (64, 8)

    // 2. gate graph conv: Y1 = A@X, Y2 = A@Y1
    sgemm_kernel<<<gemm_grid, 256>>>(A, X,  Y1, NN, BCDIM, NN);
    sgemm_kernel<<<gemm_grid, 256>>>(A, Y1, Y2, NN, BCDIM, NN);

    // 3. per-node gate weights + gate GEMM (writes X2 candidate, R)
    build_W_kernel<<<dim3(48, 64), 256>>>(gWp, E, W, 3*CC*CC);
    pernode_gate_kernel<<<NN, 256>>>(X, Y1, Y2, W, E, gbp, X2, R);

    // 4. update graph conv on candidate
    sgemm_kernel<<<gemm_grid, 256>>>(A, X2, Y1, NN, BCDIM, NN);
    sgemm_kernel<<<gemm_grid, 256>>>(A, Y1, Y2, NN, BCDIM, NN);

    // 5. per-node update weights + update GEMM + GRU combine
    build_W_kernel<<<dim3(24, 64), 256>>>(uWp, E, W, 3*CC*HH);
    pernode_upd_kernel<<<NN, 256>>>(X2, Y1, Y2, W, E, ubp, R, X, out);
}